// round 11
// baseline (speedup 1.0000x reference)
#include <cuda_runtime.h>
#include <cstdint>

#define N_ROWS   131072
#define DIM      64
#define K_CODES  1024
#define M_TILE   256
#define THREADS  256
#define BLOCKS   (N_ROWS / M_TILE)       // 512
#define CHUNK_C  512                      // codes staged per chunk
#define ESTRIDE  72                       // floats per code row in smem (288B)
#define CAND_CAP 6144
#define EPS      4e-3f                    // >= 2x worst-case tf32(trunc) dot error

typedef unsigned long long u64;
typedef unsigned int u32;

__device__ float g_partials[BLOCKS];

// smem byte offsets
#define OFF_CNT   0
#define OFF_BEST  16                      // u64[256]
#define OFF_R     2064                    // float[256]
#define OFF_H     3088                    // float[1024]
#define OFF_CAND  7184                    // u32[6144]
#define OFF_E     31872                   // float[512*72] = 147456 B
#define SMEM_TOTAL 179328

__device__ __forceinline__ void mma_tf32(float d[4], const u32 a[4], u32 b0, u32 b1) {
    asm volatile(
        "mma.sync.aligned.m16n8k8.row.col.f32.tf32.tf32.f32 "
        "{%0,%1,%2,%3}, {%4,%5,%6,%7}, {%8,%9}, {%0,%1,%2,%3};"
        : "+f"(d[0]), "+f"(d[1]), "+f"(d[2]), "+f"(d[3])
        : "r"(a[0]), "r"(a[1]), "r"(a[2]), "r"(a[3]), "r"(b0), "r"(b1));
}

// ============================================================================
// tf32 mma approx scores -> one-pass candidate collection -> exact fp32
// rescore (round-9 bit-exact chain) -> outputs.
__global__ void __launch_bounds__(THREADS, 1)
vq_main(const float* __restrict__ x, const float* __restrict__ cb,
        float* __restrict__ out)
{
    extern __shared__ char smem[];
    int*   sm_cnt  = (int*)  (smem + OFF_CNT);
    u64*   sm_best = (u64*)  (smem + OFF_BEST);
    float* sm_r    = (float*)(smem + OFF_R);
    float* sm_h    = (float*)(smem + OFF_H);
    u32*   sm_cand = (u32*)  (smem + OFF_CAND);
    float* sm_e    = (float*)(smem + OFF_E);

    const int tid  = threadIdx.x;
    const int wid  = tid >> 5;
    const int lane = tid & 31;
    const int gid  = lane >> 2;            // group id (row selector)
    const int tig  = lane & 3;             // thread-in-group (k/col selector)
    const int base = blockIdx.x * M_TILE;

    if (tid == 0) *sm_cnt = 0;
    sm_best[tid] = ~0ull;

    // ---- r = ||x||^2 per row (grouped float4 recipe: round-9-proven) ----
    {
        const float4* xp = (const float4*)(x + (size_t)(base + tid) * DIM);
        float ss = 0.0f;
#pragma unroll
        for (int q = 0; q < 16; q++) {
            float4 v = xp[q];
            ss += v.x * v.x + v.y * v.y + v.z * v.z + v.w * v.w;
        }
        sm_r[tid] = ss;
    }
    // ---- h = ||e||^2 for all 1024 codes (same grouped recipe) ----
    for (int k = tid; k < K_CODES; k += THREADS) {
        const float4* ep = (const float4*)(cb + (size_t)k * DIM);
        float ss = 0.0f;
#pragma unroll
        for (int q = 0; q < 16; q++) {
            float4 v = ep[q];
            ss += v.x * v.x + v.y * v.y + v.z * v.z + v.w * v.w;
        }
        sm_h[k] = ss;
    }

    // ---- A fragments: 2 sets x 8 ksteps x 4 regs (warp owns 32 rows) ----
    // a[fs][ks]: {A[glo][t], A[ghi][t], A[glo][t+4], A[ghi][t+4]}
    u32 a[2][8][4];
    {
        const u32* xr = (const u32*)x;
#pragma unroll
        for (int fs = 0; fs < 2; fs++) {
            const size_t rlo = (size_t)(base + 32 * wid + 16 * fs + gid) * DIM;
            const size_t rhi = rlo + 8 * DIM;
#pragma unroll
            for (int ks = 0; ks < 8; ks++) {
                const int col = 8 * ks + tig;
                a[fs][ks][0] = xr[rlo + col];
                a[fs][ks][1] = xr[rhi + col];
                a[fs][ks][2] = xr[rlo + col + 4];
                a[fs][ks][3] = xr[rhi + col + 4];
            }
        }
    }
    __syncthreads();

    // per-thread row registers
    float rreg[4], rmin[4];
#pragma unroll
    for (int i = 0; i < 4; i++) {
        rreg[i] = sm_r[32 * wid + gid + 8 * i];   // rows +0,+8,+16,+24
        rmin[i] = 3.0e38f;
    }

    // ============ 2 chunks of 512 codes ============
    for (int s = 0; s < 2; s++) {
        const int cs = s * CHUNK_C;

        // ---- stage chunk: pair-permuted rows so (j, j+4) are adjacent ----
        for (int t = tid; t < CHUNK_C; t += THREADS) {
            const float4* src = (const float4*)(cb + (size_t)(cs + t) * DIM);
            float2* dst = (float2*)(sm_e + (size_t)t * ESTRIDE);
#pragma unroll
            for (int qq = 0; qq < 8; qq++) {      // 8-wide k blocks
                float4 va = src[2 * qq], vb = src[2 * qq + 1];
                dst[4 * qq + 0] = make_float2(va.x, vb.x);   // tig 0: (j, j+4)
                dst[4 * qq + 1] = make_float2(va.y, vb.y);
                dst[4 * qq + 2] = make_float2(va.z, vb.z);
                dst[4 * qq + 3] = make_float2(va.w, vb.w);
            }
        }
        __syncthreads();

        // ---- 64 n-tiles of 8 codes ----
        for (int nt = 0; nt < CHUNK_C / 8; nt++) {
            const int kg = cs + 8 * nt;
            const float2* bp = (const float2*)(sm_e + (size_t)(8 * nt + gid) * ESTRIDE);
            const float2 h2 = *(const float2*)(sm_h + kg + 2 * tig);

            float d0[4] = {0, 0, 0, 0}, d1[4] = {0, 0, 0, 0};
#pragma unroll
            for (int ks = 0; ks < 8; ks++) {
                float2 b = bp[4 * ks + tig];      // one LDS.64 -> (k=tig, k=tig+4)
                u32 b0 = __float_as_uint(b.x), b1 = __float_as_uint(b.y);
                mma_tf32(d0, a[0][ks], b0, b1);
                mma_tf32(d1, a[1][ks], b0, b1);
            }

#pragma unroll
            for (int fs = 0; fs < 2; fs++) {
                const float* dd = fs ? d1 : d0;
                float v0 = fmaf(-2.0f, dd[0], rreg[2 * fs] + h2.x);
                float v1 = fmaf(-2.0f, dd[1], rreg[2 * fs] + h2.y);
                float v2 = fmaf(-2.0f, dd[2], rreg[2 * fs + 1] + h2.x);
                float v3 = fmaf(-2.0f, dd[3], rreg[2 * fs + 1] + h2.y);
                float mlo = fminf(v0, v1), mhi = fminf(v2, v3);
                mlo = fminf(mlo, __shfl_xor_sync(0xffffffffu, mlo, 1));
                mlo = fminf(mlo, __shfl_xor_sync(0xffffffffu, mlo, 2));
                mhi = fminf(mhi, __shfl_xor_sync(0xffffffffu, mhi, 1));
                mhi = fminf(mhi, __shfl_xor_sync(0xffffffffu, mhi, 2));
                rmin[2 * fs]     = fminf(rmin[2 * fs], mlo);
                rmin[2 * fs + 1] = fminf(rmin[2 * fs + 1], mhi);
                const float tlo = rmin[2 * fs] + EPS;
                const float thi = rmin[2 * fs + 1] + EPS;
                const int rlo = 32 * wid + 16 * fs + gid, rhi = rlo + 8;
                const int k0 = kg + 2 * tig, k1 = k0 + 1;
                // running-min threshold only shrinks => superset of final set
                if (v0 <= tlo) { int p = atomicAdd(sm_cnt, 1); if (p < CAND_CAP) sm_cand[p] = ((u32)rlo << 10) | (u32)k0; }
                if (v1 <= tlo) { int p = atomicAdd(sm_cnt, 1); if (p < CAND_CAP) sm_cand[p] = ((u32)rlo << 10) | (u32)k1; }
                if (v2 <= thi) { int p = atomicAdd(sm_cnt, 1); if (p < CAND_CAP) sm_cand[p] = ((u32)rhi << 10) | (u32)k0; }
                if (v3 <= thi) { int p = atomicAdd(sm_cnt, 1); if (p < CAND_CAP) sm_cand[p] = ((u32)rhi << 10) | (u32)k1; }
            }
        }
        __syncthreads();
    }

    // ---- exact rescore (reference fp32 chain, bit-exact per rounds 8/9) ----
    {
        int nc = *sm_cnt; if (nc > CAND_CAP) nc = CAND_CAP;
        for (int i = tid; i < nc; i += THREADS) {
            const u32 e = sm_cand[i];
            const int row = (int)(e >> 10), k = (int)(e & 1023u);
            const float4* xp = (const float4*)(x  + (size_t)(base + row) * DIM);
            const float4* ep = (const float4*)(cb + (size_t)k * DIM);
            float t = 0.0f;
#pragma unroll
            for (int q = 0; q < 16; q++) {        // strictly ascending j, one chain
                float4 va = xp[q], vb = ep[q];
                t = fmaf(va.x, vb.x, t); t = fmaf(va.y, vb.y, t);
                t = fmaf(va.z, vb.z, t); t = fmaf(va.w, vb.w, t);
            }
            const float d = fmaf(-2.0f, t, sm_r[row] + sm_h[k]);
            const u64 key = ((u64)__float_as_uint(d) << 32) | (u32)k;  // min d, then min k
            atomicMin(&sm_best[row], key);
        }
    }
    __syncthreads();

    // ---- outputs: out[0]=loss, out[1..1+N*D)=quantized_st, then indices ----
    float ls = 0.0f;
    {
        const int row = tid, n = base + row;
        const int k = (int)(u32)(sm_best[row] & 0xFFFFFFFFull);
        const float4* ep = (const float4*)(cb + (size_t)k * DIM);
        const float4* xp = (const float4*)(x + (size_t)n * DIM);
        float* qd = out + 1 + (size_t)n * DIM;    // 4B-aligned base -> scalar stores
#pragma unroll
        for (int q = 0; q < 16; q++) {
            float4 e = ep[q], v = xp[q];
            float c0 = e.x - v.x, c1 = e.y - v.y, c2 = e.z - v.z, c3 = e.w - v.w;
            ls += c0 * c0 + c1 * c1 + c2 * c2 + c3 * c3;
            qd[4 * q + 0] = v.x + c0;             // reference: x + (q - x)
            qd[4 * q + 1] = v.y + c1;
            qd[4 * q + 2] = v.z + c2;
            qd[4 * q + 3] = v.w + c3;
        }
        (out + 1 + (size_t)N_ROWS * DIM)[n] = (float)k;
    }

    // deterministic loss partial
#pragma unroll
    for (int o = 16; o > 0; o >>= 1)
        ls += __shfl_down_sync(0xffffffffu, ls, o);
    if (lane == 0) sm_r[wid] = ls;                // sm_r dead after rescore
    __syncthreads();
    if (tid == 0) {
        float t = 0.0f;
#pragma unroll
        for (int w = 0; w < 8; w++) t += sm_r[w];
        g_partials[blockIdx.x] = t;
    }
}

__global__ void vq_loss(float* __restrict__ out)
{
    __shared__ float s[BLOCKS];
    const int t = threadIdx.x;
    s[t] = g_partials[t];
    __syncthreads();
    for (int o = BLOCKS / 2; o > 0; o >>= 1) {
        if (t < o) s[t] += s[t + o];
        __syncthreads();
    }
    if (t == 0)
        out[0] = 1.25f * s[0] / (float)((size_t)N_ROWS * DIM);
}

extern "C" void kernel_launch(void* const* d_in, const int* in_sizes, int n_in,
                              void* d_out, int out_size)
{
    const float* x  = (const float*)d_in[0];   // inputs   [N, D] fp32
    const float* cb = (const float*)d_in[1];   // codebook [K, D] fp32
    float* out = (float*)d_out;

    cudaFuncSetAttribute(vq_main, cudaFuncAttributeMaxDynamicSharedMemorySize,
                         SMEM_TOTAL);
    vq_main<<<BLOCKS, THREADS, SMEM_TOTAL>>>(x, cb, out);
    vq_loss<<<1, BLOCKS>>>(out);
}